// round 11
// baseline (speedup 1.0000x reference)
#include <cuda_runtime.h>
#include <math.h>
#include <float.h>

#define BQ    8192
#define NB    2
#define NQ    (NB*BQ)
#define KNN   16
#define BALL2 0.2f
#define GR    8
#define GC    (GR*GR*GR)
#define HCELL 0.125f
#define NBLK  512
#define IMAXX 0x7fffffff
#define SLACK 1e-5f   // d2-domain safety margin, >> ulp(qn) rounding in tcut

// ---------------- scratch (no allocations allowed) ----------------
__device__ float4 g_tmpr[NQ];
__device__ float4 g_tmpp[NQ];
__device__ int    g_pcell[NQ];
__device__ int    g_cnt[NB][GC];     // statically 0; re-zeroed by scan_kernel
__device__ int    g_start[NB][GC+1];
__device__ int    g_cur[NB][GC];
__device__ float4 g_spts[NQ];        // cell-sorted ref (x,y,z,-0.5*||p||^2)
__device__ float4 g_sppk[NQ];        // pts in the SAME sorted order
__device__ double g_partial[NBLK];
__device__ int    g_done;

__device__ __forceinline__ int cid1(float v) {
    int c = (int)(v * (float)GR);
    return min(GR - 1, max(c, 0));
}

// monotonic float<->uint key map (total order preserved, handles negatives)
__device__ __forceinline__ unsigned fkey(float f) {
    unsigned u = __float_as_uint(f);
    return (u & 0x80000000u) ? ~u : (u | 0x80000000u);
}
__device__ __forceinline__ float finv(unsigned k) {
    unsigned u = (k & 0x80000000u) ? (k & 0x7fffffffu) : ~k;
    return __uint_as_float(u);
}

// ================= build stage 1: pack + count =================
__global__ void __launch_bounds__(512) packcount_kernel(
    const float* __restrict__ ref, const float* __restrict__ pts) {
    const int i = blockIdx.x * 512 + threadIdx.x;
    const int b = i >> 13;
    const int li = i & (BQ - 1);
    const float* rp = ref + (size_t)b * BQ * 3;
    const float* pp = pts + (size_t)b * BQ * 3;
    const float x = rp[3*li+0], y = rp[3*li+1], z = rp[3*li+2];
    const float n = x*x + y*y + z*z;
    g_tmpr[i] = make_float4(x, y, z, -0.5f*n);
    g_tmpp[i] = make_float4(pp[3*li+0], pp[3*li+1], pp[3*li+2], 0.0f);
    const int cell = (cid1(z) * GR + cid1(y)) * GR + cid1(x);
    g_pcell[i] = cell;
    atomicAdd(&g_cnt[b][cell], 1);
}

// ================= build stage 2: scan =================
__global__ void __launch_bounds__(512) scan_kernel() {
    __shared__ int s[GC];
    const int b = blockIdx.x, t = threadIdx.x;
    const int cnt = g_cnt[b][t];
    s[t] = cnt;
    __syncthreads();
    for (int off = 1; off < GC; off <<= 1) {
        int v = (t >= off) ? s[t - off] : 0;
        __syncthreads();
        s[t] += v;
        __syncthreads();
    }
    g_start[b][t + 1] = s[t];
    g_cur[b][t] = s[t] - cnt;
    g_cnt[b][t] = 0;
    if (t == 0) { g_start[b][0] = 0; if (b == 0) g_done = 0; }
}

// ================= build stage 3: scatter =================
__global__ void __launch_bounds__(512) scatter_kernel() {
    const int i = blockIdx.x * 512 + threadIdx.x;
    const int b = i >> 13;
    const int pos = atomicAdd(&g_cur[b][g_pcell[i]], 1);
    g_spts[b*BQ + pos] = g_tmpr[i];
    g_sppk[b*BQ + pos] = g_tmpp[i];
}

// ---------------- 3x3 symmetric eigen -> condition ratio (fp32) ----------------
__device__ __forceinline__ float cond_of_gram(
    float g00, float g01, float g02, float g11, float g12, float g22) {
    const float q  = (g00 + g11 + g22) * (1.0f/3.0f);
    const float p1 = g01*g01 + g02*g02 + g12*g12;
    const float b00 = g00 - q, b11 = g11 - q, b22 = g22 - q;
    const float p2 = b00*b00 + b11*b11 + b22*b22 + 2.0f*p1;
    float l0, l2;
    if (p2 <= 0.0f) {
        l0 = q; l2 = q;
    } else {
        const float p   = sqrtf(p2 * (1.0f/6.0f));
        const float inv = 1.0f / p;
        const float c00 = b00*inv, c01 = g01*inv, c02 = g02*inv;
        const float c11 = b11*inv, c12 = g12*inv, c22 = b22*inv;
        float detB = c00*(c11*c22 - c12*c12)
                   - c01*(c01*c22 - c12*c02)
                   + c02*(c01*c12 - c11*c02);
        float r = 0.5f * detB;
        r = fminf(1.0f, fmaxf(-1.0f, r));
        const float phi = acosf(r) * (1.0f/3.0f);
        l0 = q + 2.0f*p*cosf(phi);
        l2 = q + 2.0f*p*cosf(phi + 2.0943951023931953f);
    }
    const float s0 = sqrtf(fmaxf(l0, 0.0f));
    const float s2 = sqrtf(fmaxf(l2, 0.0f));
    return s0 / (s2 + s0);
}

// ---- scan a (2r+1)^3 clamped box: margin-hardened group bound + x-clip ----
__device__ __forceinline__ void scan_box8(
    const float4* __restrict__ sp, const int* __restrict__ st,
    float qx, float qy, float qz, float qn,
    int cx, int cy, int cz, int r, int off, int step, unsigned gmask,
    float seed, float dv[8], int iv[8]) {
#pragma unroll
    for (int j = 0; j < 8; j++) { dv[j] = FLT_MAX; iv[j] = IMAXX; }
    float B = (seed < FLT_MAX) ? seed + SLACK : FLT_MAX;
    float tcut = 0.5f * (qn - B);
    const int xlo = max(cx - r, 0), xhi = min(cx + r, GR - 1);
    for (int kz = 0; kz <= 2*r; kz++) {
        const int dz = (kz & 1) ? -((kz + 1) >> 1) : ((kz + 1) >> 1);
        const int zz = cz + dz;
        if ((unsigned)zz >= GR) continue;
        const float fz = fmaxf(fmaxf((float)zz * HCELL - qz, qz - (float)(zz+1) * HCELL), 0.0f);
        const float fz2 = fz * fz;
        for (int ky = 0; ky <= 2*r; ky++) {
            const int dy = (ky & 1) ? -((ky + 1) >> 1) : ((ky + 1) >> 1);
            const int yy = cy + dy;
            if ((unsigned)yy >= GR) continue;
            const float fy = fmaxf(fmaxf((float)yy * HCELL - qy, qy - (float)(yy+1) * HCELL), 0.0f);
            const float fyz2 = fmaf(fy, fy, fz2);
            if (fyz2 >= B) continue;                  // row-min >= bound (margin-safe)
            // x-clip: only cells overlapping the residual-radius interval
            int xl = xlo, xh = xhi;
            if (B < FLT_MAX) {
                const float span = sqrtf(B - fyz2);   // SLACK margin absorbs rounding
                xl = max(xlo, cid1(qx - span));
                xh = min(xhi, cid1(qx + span));
            }
            const int rowbase = (zz * GR + yy) * GR;
            const int j1 = st[rowbase + xh + 1];
            for (int j = st[rowbase + xl] + off; j < j1; j += step) {
                const float4 p = sp[j];
                const float t = fmaf(qx, p.x, fmaf(qy, p.y, fmaf(qz, p.z, p.w)));
                if (t > tcut) {
                    const float d2 = fmaf(-2.0f, t, qn);
                    if (d2 < dv[7]) {                  // exact insert test
                        dv[7] = d2; iv[7] = j;
#pragma unroll
                        for (int m = 7; m > 0; --m) {
                            if (dv[m] < dv[m-1]) {
                                float td = dv[m]; dv[m] = dv[m-1]; dv[m-1] = td;
                                int   ti = iv[m]; iv[m] = iv[m-1]; iv[m-1] = ti;
                            }
                        }
                        tcut = fmaxf(tcut, 0.5f * (qn - dv[7]));
                    }
                }
            }
            // group bound: 16 held values <= b1 exist -> union kth <= b1 (+SLACK)
            const unsigned kb = __reduce_max_sync(gmask, fkey(dv[1]));
            const float b1 = finv(kb);
            if (b1 < FLT_MAX) B = fminf(B, b1 + SLACK);
            tcut = fmaxf(tcut, 0.5f * (qn - B));
        }
    }
}

// ---- destructive 8-lane merge of 8-lists via redux; lane keeps rounds lg, lg+8 ----
__device__ __forceinline__ void merge8(
    float dv[8], int iv[8], unsigned gmask, int lg,
    float& kd0, int& ki0, float& kd1, int& ki1, float& kth) {
#pragma unroll
    for (int m = 0; m < KNN; m++) {
        const unsigned hb = fkey(dv[0]);
        const unsigned wb = __reduce_min_sync(gmask, hb);
        const unsigned ci = (hb == wb) ? (unsigned)iv[0] : (unsigned)IMAXX;
        const int bi = (int)__reduce_min_sync(gmask, ci);
        const float bd = finv(wb);
        if (hb == wb && iv[0] == bi) {
#pragma unroll
            for (int j = 0; j < 7; j++) { dv[j] = dv[j+1]; iv[j] = iv[j+1]; }
            dv[7] = FLT_MAX; iv[7] = IMAXX;
        }
        if (m == lg)     { kd0 = bd; ki0 = bi; }
        if (m == lg + 8) { kd1 = bd; ki1 = bi; }
        kth = bd;
    }
}

// ---- destructive 8-lane merge of TWO 8-lists per lane (16-way fallback) ----
__device__ __forceinline__ void merge16(
    float dA[8], int iA[8], float dB[8], int iB[8], unsigned gmask, int lg,
    float& kd0, int& ki0, float& kd1, int& ki1, float& kth) {
#pragma unroll
    for (int m = 0; m < KNN; m++) {
        const bool fa = (dA[0] < dB[0]) || (dA[0] == dB[0] && iA[0] < iB[0]);
        const float h = fa ? dA[0] : dB[0];
        const int  hi = fa ? iA[0] : iB[0];
        const unsigned hb = fkey(h);
        const unsigned wb = __reduce_min_sync(gmask, hb);
        const unsigned ci = (hb == wb) ? (unsigned)hi : (unsigned)IMAXX;
        const int bi = (int)__reduce_min_sync(gmask, ci);
        const float bd = finv(wb);
        if (hb == wb && hi == bi) {
            if (fa) {
#pragma unroll
                for (int j = 0; j < 7; j++) { dA[j] = dA[j+1]; iA[j] = iA[j+1]; }
                dA[7] = FLT_MAX; iA[7] = IMAXX;
            } else {
#pragma unroll
                for (int j = 0; j < 7; j++) { dB[j] = dB[j+1]; iB[j] = iB[j+1]; }
                dB[7] = FLT_MAX; iB[7] = IMAXX;
            }
        }
        if (m == lg)     { kd0 = bd; ki0 = bi; }
        if (m == lg + 8) { kd1 = bd; ki1 = bi; }
        kth = bd;
    }
}

// ---- one full exact KNN pass over box radius r (with overflow fallback) ----
__device__ __forceinline__ void knn_pass(
    const float4* __restrict__ sp, const int* __restrict__ st,
    float qx, float qy, float qz, float qn,
    int cx, int cy, int cz, int r, unsigned gmask, int lg, float seed,
    float& kd0, int& ki0, float& kd1, int& ki1, float& kth) {
    float dv[8]; int iv[8];
    scan_box8(sp, st, qx, qy, qz, qn, cx, cy, cz, r, lg, 8, gmask, seed, dv, iv);
    const float d7 = dv[7];
    merge8(dv, iv, gmask, lg, kd0, ki0, kd1, ki1, kth);
    const bool ovf = (d7 <= kth + SLACK) && (d7 < FLT_MAX);
    if (__ballot_sync(gmask, ovf)) {
        float dA[8]; int iA[8]; float dB[8]; int iB[8];
        const float sd = kth;
        scan_box8(sp, st, qx, qy, qz, qn, cx, cy, cz, r, lg,     16, gmask, sd, dA, iA);
        scan_box8(sp, st, qx, qy, qz, qn, cx, cy, cz, r, lg + 8, 16, gmask, sd, dB, iB);
        merge16(dA, iA, dB, iB, gmask, lg, kd0, ki0, kd1, ki1, kth);
    }
}

// ================= fused knn + cond + reduction =================
__global__ void __launch_bounds__(256, 3) knncond_kernel(float* __restrict__ out) {
    __shared__ double ssum[32];
    __shared__ double sred[256];
    __shared__ int    sdone;

    const int tid = threadIdx.x;
    const int lg  = tid & 7;
    const int qs  = tid >> 3;
    const unsigned gmask = 0xFFu << (tid & 24);
    const int blk = blockIdx.x;
    const int b   = blk >> 8;
    const int s   = b * BQ + (blk & 255) * 32 + qs;

    const float4 qp = g_spts[s];
    const float qx = qp.x, qy = qp.y, qz = qp.z;
    const float qn = -2.0f * qp.w;
    const int cx = cid1(qx), cy = cid1(qy), cz = cid1(qz);

    const float4* __restrict__ sp  = g_spts + b * BQ;
    const float4* __restrict__ spp = g_sppk + b * BQ;
    const int*    __restrict__ st  = g_start[b];

    float kd0, kd1, kth; int ki0, ki1;
    knn_pass(sp, st, qx, qy, qz, qn, cx, cy, cz, 1, gmask, lg, FLT_MAX,
             kd0, ki0, kd1, ki1, kth);

    // guard + rare expanding-box rescan (slacked guard, margin-safe seed)
    for (int r = 1; r < GR; r++) {
        float g = FLT_MAX;
        if (cx - r > 0)      g = fminf(g, qx - (float)(cx - r) * HCELL);
        if (cx + r < GR - 1) g = fminf(g, (float)(cx + r + 1) * HCELL - qx);
        if (cy - r > 0)      g = fminf(g, qy - (float)(cy - r) * HCELL);
        if (cy + r < GR - 1) g = fminf(g, (float)(cy + r + 1) * HCELL - qy);
        if (cz - r > 0)      g = fminf(g, qz - (float)(cz - r) * HCELL);
        if (cz + r < GR - 1) g = fminf(g, (float)(cz + r + 1) * HCELL - qz);
        if (g == FLT_MAX || kth + SLACK < g * g) break;
        knn_pass(sp, st, qx, qy, qz, qn, cx, cy, cz, r + 1, gmask, lg, kth,
                 kd0, ki0, kd1, ki1, kth);
    }

    // ---- cond phase: 2 neighbors per lane, shifted-Gram + butterfly ----
    {
        float nb = 0.0f;
        float S0r=0.f,S1r=0.f,S2r=0.f, G00r=0.f,G01r=0.f,G02r=0.f,G11r=0.f,G12r=0.f,G22r=0.f;
        float S0p=0.f,S1p=0.f,S2p=0.f, G00p=0.f,G01p=0.f,G02p=0.f,G11p=0.f,G12p=0.f,G22p=0.f;
#pragma unroll
        for (int h = 0; h < 2; h++) {
            const float d  = h ? kd1 : kd0;
            const int   id = min(h ? ki1 : ki0, BQ - 1);   // insurance clamp
            const float m = (d < BALL2) ? 1.0f : 0.0f;
            nb += m;
            const float4 pr = sp[id];
            const float ux = fmaf(m, pr.x, -qx);
            const float uy = fmaf(m, pr.y, -qy);
            const float uz = fmaf(m, pr.z, -qz);
            S0r += ux; S1r += uy; S2r += uz;
            G00r += ux*ux; G01r += ux*uy; G02r += ux*uz;
            G11r += uy*uy; G12r += uy*uz; G22r += uz*uz;
            const float4 pq = spp[id];
            const float vx = pq.x - qx;
            const float vy = pq.y - qy;
            const float vz = pq.z - qz;
            S0p += vx; S1p += vy; S2p += vz;
            G00p += vx*vx; G01p += vx*vy; G02p += vx*vz;
            G11p += vy*vy; G12p += vy*vz; G22p += vz*vz;
        }
#pragma unroll
        for (int off = 1; off < 8; off <<= 1) {
            nb   += __shfl_xor_sync(gmask, nb,   off, 8);
            S0r  += __shfl_xor_sync(gmask, S0r,  off, 8);
            S1r  += __shfl_xor_sync(gmask, S1r,  off, 8);
            S2r  += __shfl_xor_sync(gmask, S2r,  off, 8);
            G00r += __shfl_xor_sync(gmask, G00r, off, 8);
            G01r += __shfl_xor_sync(gmask, G01r, off, 8);
            G02r += __shfl_xor_sync(gmask, G02r, off, 8);
            G11r += __shfl_xor_sync(gmask, G11r, off, 8);
            G12r += __shfl_xor_sync(gmask, G12r, off, 8);
            G22r += __shfl_xor_sync(gmask, G22r, off, 8);
            S0p  += __shfl_xor_sync(gmask, S0p,  off, 8);
            S1p  += __shfl_xor_sync(gmask, S1p,  off, 8);
            S2p  += __shfl_xor_sync(gmask, S2p,  off, 8);
            G00p += __shfl_xor_sync(gmask, G00p, off, 8);
            G01p += __shfl_xor_sync(gmask, G01p, off, 8);
            G02p += __shfl_xor_sync(gmask, G02p, off, 8);
            G11p += __shfl_xor_sync(gmask, G11p, off, 8);
            G12p += __shfl_xor_sync(gmask, G12p, off, 8);
            G22p += __shfl_xor_sync(gmask, G22p, off, 8);
        }
        if (lg == 0) {
            const float invn = 1.0f / nb;
            const float ex = 16.0f - nb;
            {
                const float c0 = (S0r + ex*qx) * invn;
                const float c1 = (S1r + ex*qy) * invn;
                const float c2 = (S2r + ex*qz) * invn;
                G00r = G00r - 2.f*c0*S0r + 16.f*c0*c0;
                G11r = G11r - 2.f*c1*S1r + 16.f*c1*c1;
                G22r = G22r - 2.f*c2*S2r + 16.f*c2*c2;
                G01r = G01r - c0*S1r - c1*S0r + 16.f*c0*c1;
                G02r = G02r - c0*S2r - c2*S0r + 16.f*c0*c2;
                G12r = G12r - c1*S2r - c2*S1r + 16.f*c1*c2;
            }
            const float cond_ref = cond_of_gram(G00r,G01r,G02r,G11r,G12r,G22r);
            {
                const float c0 = (S0p + ex*qx) * invn;
                const float c1 = (S1p + ex*qy) * invn;
                const float c2 = (S2p + ex*qz) * invn;
                G00p = G00p - 2.f*c0*S0p + 16.f*c0*c0;
                G11p = G11p - 2.f*c1*S1p + 16.f*c1*c1;
                G22p = G22p - 2.f*c2*S2p + 16.f*c2*c2;
                G01p = G01p - c0*S1p - c1*S0p + 16.f*c0*c1;
                G02p = G02p - c0*S2p - c2*S0p + 16.f*c0*c2;
                G12p = G12p - c1*S2p - c2*S1p + 16.f*c1*c2;
            }
            const float cond_p = cond_of_gram(G00p,G01p,G02p,G11p,G12p,G22p);
            const double diff = (double)cond_p - (double)cond_ref;
            ssum[qs] = diff * diff;
        }
    }
    __syncthreads();

    for (int stp = 16; stp > 0; stp >>= 1) {
        if (tid < stp) ssum[tid] += ssum[tid + stp];
        __syncthreads();
    }
    if (tid == 0) g_partial[blk] = ssum[0];

    if (tid == 0) {
        __threadfence();
        const int v = atomicAdd(&g_done, 1);
        sdone = (v == NBLK - 1);
    }
    __syncthreads();
    if (sdone) {
        __threadfence();
        sred[tid] = g_partial[tid] + g_partial[tid + 256];
        __syncthreads();
        for (int stp = 128; stp > 0; stp >>= 1) {
            if (tid < stp) sred[tid] += sred[tid + stp];
            __syncthreads();
        }
        if (tid == 0) out[0] = (float)(sred[0] / (double)NQ);
    }
}

// ---------------- launch ----------------
extern "C" void kernel_launch(void* const* d_in, const int* in_sizes, int n_in,
                              void* d_out, int out_size) {
    const float* ref = (const float*)d_in[0];
    const float* pts = (const float*)d_in[1];
    packcount_kernel<<<NQ/512, 512>>>(ref, pts);
    scan_kernel<<<NB, 512>>>();
    scatter_kernel<<<NQ/512, 512>>>();
    knncond_kernel<<<NBLK, 256>>>((float*)d_out);
}

// round 12
// speedup vs baseline: 1.2303x; 1.2303x over previous
#include <cuda_runtime.h>
#include <math.h>
#include <float.h>

#define BQ    8192
#define NB    2
#define NQ    (NB*BQ)
#define KNN   16
#define BALL2 0.2f
#define GR    8
#define GC    (GR*GR*GR)
#define HCELL 0.125f
#define NBLK  512
#define IMAXX 0x7fffffff
#define SLACK 1e-5f   // d2-domain safety margin, >> ulp(qn) rounding in tcut

// ---------------- scratch (no allocations allowed) ----------------
__device__ float4 g_tmpr[NQ];
__device__ float4 g_tmpp[NQ];
__device__ int    g_pcell[NQ];
__device__ int    g_cnt[NB][GC];     // statically 0; re-zeroed by scan_kernel
__device__ int    g_start[NB][GC+1];
__device__ int    g_cur[NB][GC];
__device__ float4 g_spts[NQ];        // cell-sorted ref (x,y,z,-0.5*||p||^2)
__device__ float4 g_sppk[NQ];        // pts in the SAME sorted order
__device__ double g_partial[NBLK];
__device__ int    g_done;

__device__ __forceinline__ int cid1(float v) {
    int c = (int)(v * (float)GR);
    return min(GR - 1, max(c, 0));
}

// ================= build stage 1: pack + count =================
__global__ void __launch_bounds__(512) packcount_kernel(
    const float* __restrict__ ref, const float* __restrict__ pts) {
    const int i = blockIdx.x * 512 + threadIdx.x;
    const int b = i >> 13;
    const int li = i & (BQ - 1);
    const float* rp = ref + (size_t)b * BQ * 3;
    const float* pp = pts + (size_t)b * BQ * 3;
    const float x = rp[3*li+0], y = rp[3*li+1], z = rp[3*li+2];
    const float n = x*x + y*y + z*z;
    g_tmpr[i] = make_float4(x, y, z, -0.5f*n);
    g_tmpp[i] = make_float4(pp[3*li+0], pp[3*li+1], pp[3*li+2], 0.0f);
    const int cell = (cid1(z) * GR + cid1(y)) * GR + cid1(x);
    g_pcell[i] = cell;
    atomicAdd(&g_cnt[b][cell], 1);
}

// ================= build stage 2: scan =================
__global__ void __launch_bounds__(512) scan_kernel() {
    __shared__ int s[GC];
    const int b = blockIdx.x, t = threadIdx.x;
    const int cnt = g_cnt[b][t];
    s[t] = cnt;
    __syncthreads();
    for (int off = 1; off < GC; off <<= 1) {
        int v = (t >= off) ? s[t - off] : 0;
        __syncthreads();
        s[t] += v;
        __syncthreads();
    }
    g_start[b][t + 1] = s[t];
    g_cur[b][t] = s[t] - cnt;
    g_cnt[b][t] = 0;
    if (t == 0) { g_start[b][0] = 0; if (b == 0) g_done = 0; }
}

// ================= build stage 3: scatter =================
__global__ void __launch_bounds__(512) scatter_kernel() {
    const int i = blockIdx.x * 512 + threadIdx.x;
    const int b = i >> 13;
    const int pos = atomicAdd(&g_cur[b][g_pcell[i]], 1);
    g_spts[b*BQ + pos] = g_tmpr[i];
    g_sppk[b*BQ + pos] = g_tmpp[i];
}

// ---------------- 3x3 symmetric eigen -> condition ratio (fp32) ----------------
__device__ __forceinline__ float cond_of_gram(
    float g00, float g01, float g02, float g11, float g12, float g22) {
    const float q  = (g00 + g11 + g22) * (1.0f/3.0f);
    const float p1 = g01*g01 + g02*g02 + g12*g12;
    const float b00 = g00 - q, b11 = g11 - q, b22 = g22 - q;
    const float p2 = b00*b00 + b11*b11 + b22*b22 + 2.0f*p1;
    float l0, l2;
    if (p2 <= 0.0f) {
        l0 = q; l2 = q;
    } else {
        const float p   = sqrtf(p2 * (1.0f/6.0f));
        const float inv = 1.0f / p;
        const float c00 = b00*inv, c01 = g01*inv, c02 = g02*inv;
        const float c11 = b11*inv, c12 = g12*inv, c22 = b22*inv;
        float detB = c00*(c11*c22 - c12*c12)
                   - c01*(c01*c22 - c12*c02)
                   + c02*(c01*c12 - c11*c02);
        float r = 0.5f * detB;
        r = fminf(1.0f, fmaxf(-1.0f, r));
        const float phi = acosf(r) * (1.0f/3.0f);
        l0 = q + 2.0f*p*cosf(phi);
        l2 = q + 2.0f*p*cosf(phi + 2.0943951023931953f);
    }
    const float s0 = sqrtf(fmaxf(l0, 0.0f));
    const float s2 = sqrtf(fmaxf(l2, 0.0f));
    return s0 / (s2 + s0);
}

// ---- scan a (2r+1)^3 clamped box with margin-hardened group-bound pruning ----
__device__ __forceinline__ void scan_box8(
    const float4* __restrict__ sp, const int* __restrict__ st,
    float qx, float qy, float qz, float qn,
    int cx, int cy, int cz, int r, int off, int step, unsigned gmask,
    float seed, float dv[8], int iv[8]) {
#pragma unroll
    for (int j = 0; j < 8; j++) { dv[j] = FLT_MAX; iv[j] = IMAXX; }
    float B = (seed < FLT_MAX) ? seed + SLACK : FLT_MAX;
    float tcut = 0.5f * (qn - B);                // reject => d2 > seed (margin-safe)
    const int xlo = max(cx - r, 0), xhi = min(cx + r, GR - 1);
    for (int kz = 0; kz <= 2*r; kz++) {
        const int dz = (kz & 1) ? -((kz + 1) >> 1) : ((kz + 1) >> 1);
        const int zz = cz + dz;
        if ((unsigned)zz >= GR) continue;
        const float fz = fmaxf(fmaxf((float)zz * HCELL - qz, qz - (float)(zz+1) * HCELL), 0.0f);
        const float fz2 = fz * fz;
        for (int ky = 0; ky <= 2*r; ky++) {
            const int dy = (ky & 1) ? -((ky + 1) >> 1) : ((ky + 1) >> 1);
            const int yy = cy + dy;
            if ((unsigned)yy >= GR) continue;
            const float fy = fmaxf(fmaxf((float)yy * HCELL - qy, qy - (float)(yy+1) * HCELL), 0.0f);
            if (fmaf(fy, fy, fz2) >= B) continue;     // row-min >= bound (margin-safe)
            const int rowbase = (zz * GR + yy) * GR;
            const int j1 = st[rowbase + xhi + 1];
            for (int j = st[rowbase + xlo] + off; j < j1; j += step) {
                const float4 p = sp[j];
                const float t = fmaf(qx, p.x, fmaf(qy, p.y, fmaf(qz, p.z, p.w)));
                if (t > tcut) {
                    const float d2 = fmaf(-2.0f, t, qn);
                    if (d2 < dv[7]) {                  // exact insert test
                        dv[7] = d2; iv[7] = j;
#pragma unroll
                        for (int m = 7; m > 0; --m) {
                            if (dv[m] < dv[m-1]) {
                                float td = dv[m]; dv[m] = dv[m-1]; dv[m-1] = td;
                                int   ti = iv[m]; iv[m] = iv[m-1]; iv[m-1] = ti;
                            }
                        }
                        tcut = fmaxf(tcut, 0.5f * (qn - dv[7]));
                    }
                }
            }
            // group bound: 16 held values <= b1 exist -> union kth <= b1 (+SLACK)
            float b1 = dv[1];
#pragma unroll
            for (int o = 1; o < 8; o <<= 1)
                b1 = fmaxf(b1, __shfl_xor_sync(gmask, b1, o, 8));
            if (b1 < FLT_MAX) B = fminf(B, b1 + SLACK);
            tcut = fmaxf(tcut, 0.5f * (qn - B));
        }
    }
}

// ---- destructive 8-lane merge of 8-lists; lane keeps rounds lg, lg+8 ----
__device__ __forceinline__ void merge8(
    float dv[8], int iv[8], unsigned gmask, int lg,
    float& kd0, int& ki0, float& kd1, int& ki1, float& kth) {
#pragma unroll
    for (int m = 0; m < KNN; m++) {
        float bd = dv[0]; int bi = iv[0];
#pragma unroll
        for (int off = 1; off < 8; off <<= 1) {
            const float od = __shfl_xor_sync(gmask, bd, off, 8);
            const int   oi = __shfl_xor_sync(gmask, bi, off, 8);
            if (od < bd || (od == bd && oi < bi)) { bd = od; bi = oi; }
        }
        if (dv[0] == bd && iv[0] == bi) {
#pragma unroll
            for (int j = 0; j < 7; j++) { dv[j] = dv[j+1]; iv[j] = iv[j+1]; }
            dv[7] = FLT_MAX; iv[7] = IMAXX;
        }
        if (m == lg)     { kd0 = bd; ki0 = bi; }
        if (m == lg + 8) { kd1 = bd; ki1 = bi; }
        kth = bd;
    }
}

// ---- destructive 8-lane merge of TWO 8-lists per lane (16-way fallback) ----
__device__ __forceinline__ void merge16(
    float dA[8], int iA[8], float dB[8], int iB[8], unsigned gmask, int lg,
    float& kd0, int& ki0, float& kd1, int& ki1, float& kth) {
#pragma unroll
    for (int m = 0; m < KNN; m++) {
        const bool fa = (dA[0] < dB[0]) || (dA[0] == dB[0] && iA[0] < iB[0]);
        float md = fa ? dA[0] : dB[0];
        int   mi = fa ? iA[0] : iB[0];
        float bd = md; int bi = mi;
#pragma unroll
        for (int off = 1; off < 8; off <<= 1) {
            const float od = __shfl_xor_sync(gmask, bd, off, 8);
            const int   oi = __shfl_xor_sync(gmask, bi, off, 8);
            if (od < bd || (od == bd && oi < bi)) { bd = od; bi = oi; }
        }
        if (md == bd && mi == bi) {
            if (fa) {
#pragma unroll
                for (int j = 0; j < 7; j++) { dA[j] = dA[j+1]; iA[j] = iA[j+1]; }
                dA[7] = FLT_MAX; iA[7] = IMAXX;
            } else {
#pragma unroll
                for (int j = 0; j < 7; j++) { dB[j] = dB[j+1]; iB[j] = iB[j+1]; }
                dB[7] = FLT_MAX; iB[7] = IMAXX;
            }
        }
        if (m == lg)     { kd0 = bd; ki0 = bi; }
        if (m == lg + 8) { kd1 = bd; ki1 = bi; }
        kth = bd;
    }
}

// ---- one full exact KNN pass over box radius r (with overflow fallback) ----
__device__ __forceinline__ void knn_pass(
    const float4* __restrict__ sp, const int* __restrict__ st,
    float qx, float qy, float qz, float qn,
    int cx, int cy, int cz, int r, unsigned gmask, int lg, float seed,
    float& kd0, int& ki0, float& kd1, int& ki1, float& kth) {
    float dv[8]; int iv[8];
    scan_box8(sp, st, qx, qy, qz, qn, cx, cy, cz, r, lg, 8, gmask, seed, dv, iv);
    const float d7 = dv[7];
    merge8(dv, iv, gmask, lg, kd0, ki0, kd1, ki1, kth);
    // slacked detection: any loss implies final d7 < true_kth + SLACK <= kth + SLACK
    const bool ovf = (d7 <= kth + SLACK) && (d7 < FLT_MAX);
    if (__ballot_sync(gmask, ovf)) {
        float dA[8]; int iA[8]; float dB[8]; int iB[8];
        const float sd = kth;
        scan_box8(sp, st, qx, qy, qz, qn, cx, cy, cz, r, lg,     16, gmask, sd, dA, iA);
        scan_box8(sp, st, qx, qy, qz, qn, cx, cy, cz, r, lg + 8, 16, gmask, sd, dB, iB);
        merge16(dA, iA, dB, iB, gmask, lg, kd0, ki0, kd1, ki1, kth);
    }
}

// ================= fused knn + cond + reduction =================
// ONE change vs round 10: __launch_bounds__(256, 4) -> 64 regs -> 4 blocks/SM.
__global__ void __launch_bounds__(256, 4) knncond_kernel(float* __restrict__ out) {
    __shared__ double ssum[32];
    __shared__ double sred[256];
    __shared__ int    sdone;

    const int tid = threadIdx.x;
    const int lg  = tid & 7;
    const int qs  = tid >> 3;
    const unsigned gmask = 0xFFu << (tid & 24);
    const int blk = blockIdx.x;
    const int b   = blk >> 8;
    const int s   = b * BQ + (blk & 255) * 32 + qs;

    const float4 qp = g_spts[s];
    const float qx = qp.x, qy = qp.y, qz = qp.z;
    const float qn = -2.0f * qp.w;
    const int cx = cid1(qx), cy = cid1(qy), cz = cid1(qz);

    const float4* __restrict__ sp  = g_spts + b * BQ;
    const float4* __restrict__ spp = g_sppk + b * BQ;
    const int*    __restrict__ st  = g_start[b];

    float kd0, kd1, kth; int ki0, ki1;
    knn_pass(sp, st, qx, qy, qz, qn, cx, cy, cz, 1, gmask, lg, FLT_MAX,
             kd0, ki0, kd1, ki1, kth);

    // guard + rare expanding-box rescan (slacked guard, margin-safe seed)
    for (int r = 1; r < GR; r++) {
        float g = FLT_MAX;
        if (cx - r > 0)      g = fminf(g, qx - (float)(cx - r) * HCELL);
        if (cx + r < GR - 1) g = fminf(g, (float)(cx + r + 1) * HCELL - qx);
        if (cy - r > 0)      g = fminf(g, qy - (float)(cy - r) * HCELL);
        if (cy + r < GR - 1) g = fminf(g, (float)(cy + r + 1) * HCELL - qy);
        if (cz - r > 0)      g = fminf(g, qz - (float)(cz - r) * HCELL);
        if (cz + r < GR - 1) g = fminf(g, (float)(cz + r + 1) * HCELL - qz);
        if (g == FLT_MAX || kth + SLACK < g * g) break;
        knn_pass(sp, st, qx, qy, qz, qn, cx, cy, cz, r + 1, gmask, lg, kth,
                 kd0, ki0, kd1, ki1, kth);
    }

    // ---- cond phase: 2 neighbors per lane, shifted-Gram + butterfly ----
    {
        float nb = 0.0f;
        float S0r=0.f,S1r=0.f,S2r=0.f, G00r=0.f,G01r=0.f,G02r=0.f,G11r=0.f,G12r=0.f,G22r=0.f;
        float S0p=0.f,S1p=0.f,S2p=0.f, G00p=0.f,G01p=0.f,G02p=0.f,G11p=0.f,G12p=0.f,G22p=0.f;
#pragma unroll
        for (int h = 0; h < 2; h++) {
            const float d  = h ? kd1 : kd0;
            const int   id = min(h ? ki1 : ki0, BQ - 1);   // insurance clamp
            const float m = (d < BALL2) ? 1.0f : 0.0f;
            nb += m;
            const float4 pr = sp[id];
            const float ux = fmaf(m, pr.x, -qx);
            const float uy = fmaf(m, pr.y, -qy);
            const float uz = fmaf(m, pr.z, -qz);
            S0r += ux; S1r += uy; S2r += uz;
            G00r += ux*ux; G01r += ux*uy; G02r += ux*uz;
            G11r += uy*uy; G12r += uy*uz; G22r += uz*uz;
            const float4 pq = spp[id];
            const float vx = pq.x - qx;
            const float vy = pq.y - qy;
            const float vz = pq.z - qz;
            S0p += vx; S1p += vy; S2p += vz;
            G00p += vx*vx; G01p += vx*vy; G02p += vx*vz;
            G11p += vy*vy; G12p += vy*vz; G22p += vz*vz;
        }
#pragma unroll
        for (int off = 1; off < 8; off <<= 1) {
            nb   += __shfl_xor_sync(gmask, nb,   off, 8);
            S0r  += __shfl_xor_sync(gmask, S0r,  off, 8);
            S1r  += __shfl_xor_sync(gmask, S1r,  off, 8);
            S2r  += __shfl_xor_sync(gmask, S2r,  off, 8);
            G00r += __shfl_xor_sync(gmask, G00r, off, 8);
            G01r += __shfl_xor_sync(gmask, G01r, off, 8);
            G02r += __shfl_xor_sync(gmask, G02r, off, 8);
            G11r += __shfl_xor_sync(gmask, G11r, off, 8);
            G12r += __shfl_xor_sync(gmask, G12r, off, 8);
            G22r += __shfl_xor_sync(gmask, G22r, off, 8);
            S0p  += __shfl_xor_sync(gmask, S0p,  off, 8);
            S1p  += __shfl_xor_sync(gmask, S1p,  off, 8);
            S2p  += __shfl_xor_sync(gmask, S2p,  off, 8);
            G00p += __shfl_xor_sync(gmask, G00p, off, 8);
            G01p += __shfl_xor_sync(gmask, G01p, off, 8);
            G02p += __shfl_xor_sync(gmask, G02p, off, 8);
            G11p += __shfl_xor_sync(gmask, G11p, off, 8);
            G12p += __shfl_xor_sync(gmask, G12p, off, 8);
            G22p += __shfl_xor_sync(gmask, G22p, off, 8);
        }
        if (lg == 0) {
            const float invn = 1.0f / nb;
            const float ex = 16.0f - nb;
            {
                const float c0 = (S0r + ex*qx) * invn;
                const float c1 = (S1r + ex*qy) * invn;
                const float c2 = (S2r + ex*qz) * invn;
                G00r = G00r - 2.f*c0*S0r + 16.f*c0*c0;
                G11r = G11r - 2.f*c1*S1r + 16.f*c1*c1;
                G22r = G22r - 2.f*c2*S2r + 16.f*c2*c2;
                G01r = G01r - c0*S1r - c1*S0r + 16.f*c0*c1;
                G02r = G02r - c0*S2r - c2*S0r + 16.f*c0*c2;
                G12r = G12r - c1*S2r - c2*S1r + 16.f*c1*c2;
            }
            const float cond_ref = cond_of_gram(G00r,G01r,G02r,G11r,G12r,G22r);
            {
                const float c0 = (S0p + ex*qx) * invn;
                const float c1 = (S1p + ex*qy) * invn;
                const float c2 = (S2p + ex*qz) * invn;
                G00p = G00p - 2.f*c0*S0p + 16.f*c0*c0;
                G11p = G11p - 2.f*c1*S1p + 16.f*c1*c1;
                G22p = G22p - 2.f*c2*S2p + 16.f*c2*c2;
                G01p = G01p - c0*S1p - c1*S0p + 16.f*c0*c1;
                G02p = G02p - c0*S2p - c2*S0p + 16.f*c0*c2;
                G12p = G12p - c1*S2p - c2*S1p + 16.f*c1*c2;
            }
            const float cond_p = cond_of_gram(G00p,G01p,G02p,G11p,G12p,G22p);
            const double diff = (double)cond_p - (double)cond_ref;
            ssum[qs] = diff * diff;
        }
    }
    __syncthreads();

    for (int stp = 16; stp > 0; stp >>= 1) {
        if (tid < stp) ssum[tid] += ssum[tid + stp];
        __syncthreads();
    }
    if (tid == 0) g_partial[blk] = ssum[0];

    if (tid == 0) {
        __threadfence();
        const int v = atomicAdd(&g_done, 1);
        sdone = (v == NBLK - 1);
    }
    __syncthreads();
    if (sdone) {
        __threadfence();
        sred[tid] = g_partial[tid] + g_partial[tid + 256];
        __syncthreads();
        for (int stp = 128; stp > 0; stp >>= 1) {
            if (tid < stp) sred[tid] += sred[tid + stp];
            __syncthreads();
        }
        if (tid == 0) out[0] = (float)(sred[0] / (double)NQ);
    }
}

// ---------------- launch ----------------
extern "C" void kernel_launch(void* const* d_in, const int* in_sizes, int n_in,
                              void* d_out, int out_size) {
    const float* ref = (const float*)d_in[0];
    const float* pts = (const float*)d_in[1];
    packcount_kernel<<<NQ/512, 512>>>(ref, pts);
    scan_kernel<<<NB, 512>>>();
    scatter_kernel<<<NQ/512, 512>>>();
    knncond_kernel<<<NBLK, 256>>>((float*)d_out);
}